// round 1
// baseline (speedup 1.0000x reference)
#include <cuda_runtime.h>

#define Nn 50000
#define Ff 16
#define Tt 12
#define Hh 64
#define Ee 1600000
#define FT (Ff*Tt)   // 192

// ---------------- scratch (static device globals; allocation-free) -----------
__device__ float g_deg[Nn];
__device__ float g_dis[Nn];
__device__ float g_selfn[Nn];
__device__ float g_ewn[Ee];
__device__ float g_xT[Nn*FT];      // x transposed to [N][T][F]
__device__ float g_Px[Nn*FT];      // A_hat @ x, layout [N][T][F]
__device__ float g_h[Nn*Hh];
__device__ float g_Ph[Nn*Hh];      // A_hat @ h
__device__ float g_z[Nn*Hh];
__device__ float g_rh[Nn*Hh];      // r * h
__device__ float g_Prh[Nn*Hh];     // A_hat @ (r*h)
__device__ float g_hs[Nn*Tt*Hh];   // hidden states [N][T][H]

// ---------------- helpers ----------------------------------------------------
__device__ __forceinline__ void red_add_v4(float* addr, float a, float b, float c, float d) {
    asm volatile("red.global.add.v4.f32 [%0], {%1,%2,%3,%4};"
                 :: "l"(addr), "f"(a), "f"(b), "f"(c), "f"(d) : "memory");
}
__device__ __forceinline__ float fsigmoid(float x) { return 1.f / (1.f + __expf(-x)); }
__device__ __forceinline__ float ftanh(float x)    { return 1.f - 2.f / (__expf(2.f*x) + 1.f); }

// ---------------- setup kernels ----------------------------------------------
__global__ void k_init() {
    int i = blockIdx.x * blockDim.x + threadIdx.x;
    if (i < Nn) g_deg[i] = 1.f;
    if (i < Nn*Hh) { g_h[i] = 0.f; g_Ph[i] = 0.f; }
}

__global__ void k_deg(const int* __restrict__ ei, const float* __restrict__ w) {
    int e = blockIdx.x * blockDim.x + threadIdx.x;
    if (e < Ee) atomicAdd(&g_deg[ei[Ee + e]], w[e]);
}

__global__ void k_norm() {
    int i = blockIdx.x * blockDim.x + threadIdx.x;
    if (i < Nn) { float d = g_deg[i]; g_dis[i] = rsqrtf(d); g_selfn[i] = 1.f / d; }
}

__global__ void k_ewn(const int* __restrict__ ei, const float* __restrict__ w) {
    int e = blockIdx.x * blockDim.x + threadIdx.x;
    if (e < Ee) g_ewn[e] = g_dis[ei[e]] * w[e] * g_dis[ei[Ee + e]];
}

// transpose x [N][F][T] -> xT [N][T][F]; also seed Px with self-loop term
__global__ void k_xT(const float* __restrict__ x) {
    int i = blockIdx.x * blockDim.x + threadIdx.x;
    if (i >= Nn*FT) return;
    int n = i / FT, r = i % FT, f = r / Tt, t = r % Tt;
    float v = x[i];
    int o = n*FT + t*Ff + f;
    g_xT[o] = v;
    g_Px[o] = g_selfn[n] * v;
}

// ---------------- edge propagation -------------------------------------------
// propagate 192 cols: xT -> Px (red-accumulate on top of self-term)
__global__ void k_prop192(const int* __restrict__ ei) {
    const int VP = FT/4;  // 48
    unsigned gid = blockIdx.x * blockDim.x + threadIdx.x;
    if (gid >= (unsigned)Ee * VP) return;
    int e = gid / VP;
    int j = gid - e*VP;
    int s = ei[e], d = ei[Ee + e];
    float w = g_ewn[e];
    const float4 v = *(const float4*)(g_xT + s*FT + 4*j);
    red_add_v4(g_Px + d*FT + 4*j, v.x*w, v.y*w, v.z*w, v.w*w);
}

// propagate 64 cols: which=0: h->Ph, which=1: rh->Prh
__global__ void k_prop64(const int* __restrict__ ei, int which) {
    const int VP = Hh/4;  // 16
    unsigned gid = blockIdx.x * blockDim.x + threadIdx.x;
    if (gid >= (unsigned)Ee * VP) return;
    int e = gid / VP;
    int j = gid - e*VP;
    int s = ei[e], d = ei[Ee + e];
    float w = g_ewn[e];
    const float* X = which ? g_rh : g_h;
    float* Y       = which ? g_Prh : g_Ph;
    const float4 v = *(const float4*)(X + s*Hh + 4*j);
    red_add_v4(Y + d*Hh + 4*j, v.x*w, v.y*w, v.z*w, v.w*w);
}

// ---------------- GRU gate kernels -------------------------------------------
// z,r = sigmoid([Px_t, Ph] @ [Wz|Wr] + [bz|br]); also rh=r*h, Prh seeded self term
__global__ __launch_bounds__(256) void k_gates(
    const float* __restrict__ Wz, const float* __restrict__ bz,
    const float* __restrict__ Wr, const float* __restrict__ br, int t)
{
    __shared__ float xin[16*80];
    __shared__ float Wsh[80*128];
    __shared__ float bsh[128];
    int tid = threadIdx.x;
    int nb = blockIdx.x * 16;

    for (int i = tid; i < 80*128; i += 256) {
        int k = i >> 7, c = i & 127;
        Wsh[i] = (c < 64) ? Wz[k*64 + c] : Wr[k*64 + (c - 64)];
    }
    if (tid < 128) bsh[tid] = (tid < 64) ? bz[tid] : br[tid - 64];
    for (int i = tid; i < 16*80; i += 256) {
        int nl = i / 80, k = i - nl*80;
        int n = nb + nl;
        xin[i] = (k < Ff) ? g_Px[n*FT + t*Ff + k] : g_Ph[n*Hh + (k - Ff)];
    }
    __syncthreads();

    int col4 = (tid & 31) * 4;   // 0..124, warp-varying
    int nr   = tid >> 5;         // 0..7, warp-uniform
    float acc[2][4];
    #pragma unroll
    for (int i = 0; i < 2; i++)
        #pragma unroll
        for (int q = 0; q < 4; q++) acc[i][q] = bsh[col4 + q];

    #pragma unroll 4
    for (int k = 0; k < 80; k++) {
        float4 wv = *(const float4*)&Wsh[k*128 + col4];
        float x0 = xin[(nr*2 + 0)*80 + k];
        float x1 = xin[(nr*2 + 1)*80 + k];
        acc[0][0] += x0*wv.x; acc[0][1] += x0*wv.y; acc[0][2] += x0*wv.z; acc[0][3] += x0*wv.w;
        acc[1][0] += x1*wv.x; acc[1][1] += x1*wv.y; acc[1][2] += x1*wv.z; acc[1][3] += x1*wv.w;
    }

    #pragma unroll
    for (int i = 0; i < 2; i++) {
        int n = nb + nr*2 + i;
        float4 sv;
        sv.x = fsigmoid(acc[i][0]); sv.y = fsigmoid(acc[i][1]);
        sv.z = fsigmoid(acc[i][2]); sv.w = fsigmoid(acc[i][3]);
        if (col4 < 64) {
            *(float4*)&g_z[n*Hh + col4] = sv;
        } else {
            int c = col4 - 64;
            float4 hv = *(const float4*)&g_h[n*Hh + c];
            float sn = g_selfn[n];
            float4 rh; rh.x = sv.x*hv.x; rh.y = sv.y*hv.y; rh.z = sv.z*hv.z; rh.w = sv.w*hv.w;
            *(float4*)&g_rh[n*Hh + c] = rh;
            float4 pv; pv.x = sn*rh.x; pv.y = sn*rh.y; pv.z = sn*rh.z; pv.w = sn*rh.w;
            *(float4*)&g_Prh[n*Hh + c] = pv;
        }
    }
}

// hc = tanh([Px_t, Prh] @ Wh + bh); h = z*h + (1-z)*hc; store hs; seed Ph for next step
__global__ __launch_bounds__(256) void k_final(
    const float* __restrict__ Wh, const float* __restrict__ bh, int t)
{
    __shared__ float xin[32*80];
    __shared__ float Wsh[80*64];
    __shared__ float bsh[64];
    int tid = threadIdx.x;
    int nb = blockIdx.x * 32;

    for (int i = tid; i < 80*64; i += 256) Wsh[i] = Wh[i];
    if (tid < 64) bsh[tid] = bh[tid];
    for (int i = tid; i < 32*80; i += 256) {
        int nl = i / 80, k = i - nl*80;
        int n = nb + nl;
        float v = 0.f;
        if (n < Nn) v = (k < Ff) ? g_Px[n*FT + t*Ff + k] : g_Prh[n*Hh + (k - Ff)];
        xin[i] = v;
    }
    __syncthreads();

    int col4 = (tid & 15) * 4;   // 0..60
    int nr   = tid >> 4;         // 0..15
    float acc[2][4];
    #pragma unroll
    for (int i = 0; i < 2; i++)
        #pragma unroll
        for (int q = 0; q < 4; q++) acc[i][q] = bsh[col4 + q];

    #pragma unroll 4
    for (int k = 0; k < 80; k++) {
        float4 wv = *(const float4*)&Wsh[k*64 + col4];
        float x0 = xin[(nr*2 + 0)*80 + k];
        float x1 = xin[(nr*2 + 1)*80 + k];
        acc[0][0] += x0*wv.x; acc[0][1] += x0*wv.y; acc[0][2] += x0*wv.z; acc[0][3] += x0*wv.w;
        acc[1][0] += x1*wv.x; acc[1][1] += x1*wv.y; acc[1][2] += x1*wv.z; acc[1][3] += x1*wv.w;
    }

    #pragma unroll
    for (int i = 0; i < 2; i++) {
        int n = nb + nr*2 + i;
        if (n >= Nn) continue;
        float4 zv = *(const float4*)&g_z[n*Hh + col4];
        float4 hv = *(const float4*)&g_h[n*Hh + col4];
        float sn = g_selfn[n];
        float4 hn;
        hn.x = zv.x*hv.x + (1.f - zv.x)*ftanh(acc[i][0]);
        hn.y = zv.y*hv.y + (1.f - zv.y)*ftanh(acc[i][1]);
        hn.z = zv.z*hv.z + (1.f - zv.z)*ftanh(acc[i][2]);
        hn.w = zv.w*hv.w + (1.f - zv.w)*ftanh(acc[i][3]);
        *(float4*)&g_h[n*Hh + col4] = hn;
        *(float4*)&g_hs[n*(Tt*Hh) + t*Hh + col4] = hn;
        float4 pv; pv.x = sn*hn.x; pv.y = sn*hn.y; pv.z = sn*hn.z; pv.w = sn*hn.w;
        *(float4*)&g_Ph[n*Hh + col4] = pv;
    }
}

// ---------------- temporal attention + FC ------------------------------------
__global__ __launch_bounds__(256) void k_attn(
    const float* __restrict__ Wa, const float* __restrict__ ba,
    const float* __restrict__ cv, const float* __restrict__ Wfc,
    const float* __restrict__ bfc, float* __restrict__ out)
{
    __shared__ float Wa_sh[64*64];       // 16 KB
    __shared__ float hs_sh[4][Tt*64];    // 12 KB
    __shared__ float part[4][64*Tt];     // 12 KB, layout [q][t]
    __shared__ float al_sh[4][Tt];
    __shared__ float cv_sh[64], ba_sh[64], Wfc_sh[64];
    __shared__ float redbuf[4][2];

    int tid = threadIdx.x;
    int nl  = tid >> 6;      // node within block 0..3
    int j   = tid & 63;      // H column
    int n   = blockIdx.x * 4 + nl;
    bool valid = n < Nn;

    for (int i = tid; i < 4096; i += 256) Wa_sh[i] = Wa[i];
    if (tid < 64) { cv_sh[tid] = cv[tid]; ba_sh[tid] = ba[tid]; Wfc_sh[tid] = Wfc[tid]; }
    #pragma unroll
    for (int t = 0; t < Tt; t++)
        hs_sh[nl][t*64 + j] = valid ? g_hs[n*(Tt*Hh) + t*Hh + j] : 0.f;
    __syncthreads();

    // score/align partials
    #pragma unroll
    for (int t = 0; t < Tt; t++) {
        float acc = ba_sh[j];
        #pragma unroll 8
        for (int k = 0; k < 64; k++)
            acc += hs_sh[nl][t*64 + k] * Wa_sh[k*64 + j];
        part[nl][j*Tt + t] = ftanh(acc) * cv_sh[j];
    }
    __syncthreads();

    if (j < Tt) {
        float s = 0.f;
        #pragma unroll
        for (int q = 0; q < 64; q++) s += part[nl][q*Tt + j];
        al_sh[nl][j] = s;
    }
    __syncthreads();

    if (j == 0) {
        float m = -1e30f;
        #pragma unroll
        for (int t = 0; t < Tt; t++) m = fmaxf(m, al_sh[nl][t]);
        float e[Tt], ssum = 0.f;
        #pragma unroll
        for (int t = 0; t < Tt; t++) { e[t] = __expf(al_sh[nl][t] - m); ssum += e[t]; }
        float inv = 1.f / ssum;
        #pragma unroll
        for (int t = 0; t < Tt; t++) al_sh[nl][t] = e[t] * inv;
    }
    __syncthreads();

    float ctx = 0.f;
    #pragma unroll
    for (int t = 0; t < Tt; t++) ctx += al_sh[nl][t] * hs_sh[nl][t*64 + j];
    float o = ctx * Wfc_sh[j];
    #pragma unroll
    for (int off = 16; off; off >>= 1) o += __shfl_down_sync(0xffffffffu, o, off);
    if ((tid & 31) == 0) redbuf[nl][(tid >> 5) & 1] = o;
    __syncthreads();
    if (j == 0 && valid) out[n] = redbuf[nl][0] + redbuf[nl][1] + bfc[0];
}

// ---------------- launch ------------------------------------------------------
extern "C" void kernel_launch(void* const* d_in, const int* in_sizes, int n_in,
                              void* d_out, int out_size) {
    const float* x   = (const float*)d_in[0];
    const int*   ei  = (const int*)  d_in[1];
    const float* ew  = (const float*)d_in[2];
    const float* Wz  = (const float*)d_in[3];
    const float* bz  = (const float*)d_in[4];
    const float* Wr  = (const float*)d_in[5];
    const float* br  = (const float*)d_in[6];
    const float* Wh  = (const float*)d_in[7];
    const float* bh  = (const float*)d_in[8];
    const float* Wa  = (const float*)d_in[9];
    const float* ba  = (const float*)d_in[10];
    const float* cv  = (const float*)d_in[11];
    const float* Wfc = (const float*)d_in[12];
    const float* bfc = (const float*)d_in[13];
    float* out = (float*)d_out;

    k_init<<<(Nn*Hh + 255)/256, 256>>>();
    k_deg <<<(Ee + 255)/256, 256>>>(ei, ew);
    k_norm<<<(Nn + 255)/256, 256>>>();
    k_ewn <<<(Ee + 255)/256, 256>>>(ei, ew);
    k_xT  <<<(Nn*FT + 255)/256, 256>>>(x);
    k_prop192<<<(Ee*48 + 255)/256, 256>>>(ei);

    const int propBlocks = (Ee*16 + 255)/256;
    for (int t = 0; t < Tt; t++) {
        if (t > 0) k_prop64<<<propBlocks, 256>>>(ei, 0);            // h -> Ph
        k_gates<<<Nn/16, 256>>>(Wz, bz, Wr, br, t);                 // z, r, rh
        if (t > 0) k_prop64<<<propBlocks, 256>>>(ei, 1);            // rh -> Prh
        k_final<<<(Nn + 31)/32, 256>>>(Wh, bh, t);                  // hc, h, hs
    }

    k_attn<<<(Nn + 3)/4, 256>>>(Wa, ba, cv, Wfc, bfc, out);
}

// round 3
// speedup vs baseline: 1.5452x; 1.5452x over previous
#include <cuda_runtime.h>

#define Nn 50000
#define Ff 16
#define Tt 12
#define Hh 64
#define Ee 1600000
#define FT (Ff*Tt)   // 192
#define SCAN_TPB 1024

// ---------------- scratch (static device globals; allocation-free) -----------
__device__ float g_deg[Nn];
__device__ float g_dis[Nn];
__device__ float g_selfn[Nn];
__device__ float g_ewn[Ee];
__device__ int   g_cnt[Nn];        // per-dst degree counts
__device__ int   g_rowptr[Nn+1];   // CSR row pointers (by dst)
__device__ int   g_off[Nn];        // scatter cursors
__device__ int   g_csrc[Ee];       // CSR src indices
__device__ float g_cw[Ee];         // CSR normalized weights
__device__ float g_xT[Nn*FT];      // x transposed to [N][T][F]
__device__ float g_Px[Nn*FT];      // A_hat @ x, layout [N][T][F]
__device__ float g_h[Nn*Hh];
__device__ float g_Ph[Nn*Hh];      // A_hat @ h
__device__ float g_z[Nn*Hh];
__device__ float g_rh[Nn*Hh];      // r * h
__device__ float g_Prh[Nn*Hh];     // A_hat @ (r*h)
__device__ float g_hs[Nn*Tt*Hh];   // hidden states [N][T][H]

// ---------------- helpers ----------------------------------------------------
__device__ __forceinline__ float fsigmoid(float x) { return 1.f / (1.f + __expf(-x)); }
__device__ __forceinline__ float ftanh(float x)    { return 1.f - 2.f / (__expf(2.f*x) + 1.f); }

// ---------------- setup kernels ----------------------------------------------
__global__ void k_init() {
    int i = blockIdx.x * blockDim.x + threadIdx.x;
    if (i < Nn) { g_deg[i] = 1.f; g_cnt[i] = 0; }
    if (i < Nn*Hh) { g_h[i] = 0.f; g_Ph[i] = 0.f; g_Prh[i] = 0.f; }
}

// degree (weighted, for normalization) + histogram (counts, for CSR)
__global__ void k_deg(const int* __restrict__ ei, const float* __restrict__ w) {
    int e = blockIdx.x * blockDim.x + threadIdx.x;
    if (e < Ee) {
        int d = ei[Ee + e];
        atomicAdd(&g_deg[d], w[e]);
        atomicAdd(&g_cnt[d], 1);
    }
}

__global__ void k_norm() {
    int i = blockIdx.x * blockDim.x + threadIdx.x;
    if (i < Nn) { float d = g_deg[i]; g_dis[i] = rsqrtf(d); g_selfn[i] = 1.f / d; }
}

__global__ void k_ewn(const int* __restrict__ ei, const float* __restrict__ w) {
    int e = blockIdx.x * blockDim.x + threadIdx.x;
    if (e < Ee) g_ewn[e] = g_dis[ei[e]] * w[e] * g_dis[ei[Ee + e]];
}

// single-block exclusive scan of g_cnt -> g_rowptr, g_off
__global__ __launch_bounds__(SCAN_TPB) void k_scan() {
    __shared__ int sh[SCAN_TPB];
    const int CH = (Nn + SCAN_TPB - 1) / SCAN_TPB;  // 49
    int t = threadIdx.x;
    int base = t * CH;
    int sum = 0;
    for (int i = 0; i < CH; i++) {
        int idx = base + i;
        if (idx < Nn) sum += g_cnt[idx];
    }
    sh[t] = sum;
    __syncthreads();
    for (int off = 1; off < SCAN_TPB; off <<= 1) {
        int v = (t >= off) ? sh[t - off] : 0;
        __syncthreads();
        sh[t] += v;
        __syncthreads();
    }
    int run = (t > 0) ? sh[t - 1] : 0;
    for (int i = 0; i < CH; i++) {
        int idx = base + i;
        if (idx < Nn) {
            int c = g_cnt[idx];
            g_rowptr[idx] = run;
            g_off[idx]    = run;
            run += c;
        }
    }
    if (t == SCAN_TPB - 1) g_rowptr[Nn] = run;
}

__global__ void k_scatter(const int* __restrict__ ei) {
    int e = blockIdx.x * blockDim.x + threadIdx.x;
    if (e < Ee) {
        int d = ei[Ee + e];
        int pos = atomicAdd(&g_off[d], 1);
        g_csrc[pos] = ei[e];
        g_cw[pos]   = g_ewn[e];
    }
}

// transpose x [N][F][T] -> xT [N][T][F]
__global__ void k_xT(const float* __restrict__ x) {
    int i = blockIdx.x * blockDim.x + threadIdx.x;
    if (i >= Nn*FT) return;
    int n = i / FT, r = i % FT, f = r / Tt, t = r % Tt;
    g_xT[n*FT + t*Ff + f] = x[i];
}

// ---------------- CSR pull-mode propagation ----------------------------------
// which=0: h->Ph, which=1: rh->Prh
// Y[d] = selfn[d]*X[d] + sum_{e in row d} w[e] * X[src[e]]   (64-col rows)
__global__ __launch_bounds__(256) void k_prop64_csr(int which) {
    const float* __restrict__ X = which ? g_rh  : g_h;
    float*       __restrict__ Y = which ? g_Prh : g_Ph;
    int tid = threadIdx.x;
    int g = tid >> 4;          // 16 nodes per block
    int j = tid & 15;          // col group (float4)
    int d = blockIdx.x * 16 + g;
    if (d >= Nn) return;
    int c = 4*j;
    int beg = g_rowptr[d], end = g_rowptr[d+1];

    float sn = g_selfn[d];
    float4 a = *(const float4*)(X + d*Hh + c);
    float4 acc;
    acc.x = sn*a.x; acc.y = sn*a.y; acc.z = sn*a.z; acc.w = sn*a.w;

    int e = beg;
    for (; e + 4 <= end; e += 4) {
        int   s0 = g_csrc[e],   s1 = g_csrc[e+1], s2 = g_csrc[e+2], s3 = g_csrc[e+3];
        float w0 = g_cw[e],     w1 = g_cw[e+1],   w2 = g_cw[e+2],   w3 = g_cw[e+3];
        float4 v0 = *(const float4*)(X + s0*Hh + c);
        float4 v1 = *(const float4*)(X + s1*Hh + c);
        float4 v2 = *(const float4*)(X + s2*Hh + c);
        float4 v3 = *(const float4*)(X + s3*Hh + c);
        acc.x += w0*v0.x; acc.y += w0*v0.y; acc.z += w0*v0.z; acc.w += w0*v0.w;
        acc.x += w1*v1.x; acc.y += w1*v1.y; acc.z += w1*v1.z; acc.w += w1*v1.w;
        acc.x += w2*v2.x; acc.y += w2*v2.y; acc.z += w2*v2.z; acc.w += w2*v2.w;
        acc.x += w3*v3.x; acc.y += w3*v3.y; acc.z += w3*v3.z; acc.w += w3*v3.w;
    }
    for (; e < end; e++) {
        int s = g_csrc[e]; float w = g_cw[e];
        float4 v = *(const float4*)(X + s*Hh + c);
        acc.x += w*v.x; acc.y += w*v.y; acc.z += w*v.z; acc.w += w*v.w;
    }
    *(float4*)(Y + d*Hh + c) = acc;
}

// 192-col version: xT -> Px, 3 chunks of 64 per edge (reuses (src,w) loads)
__global__ __launch_bounds__(256) void k_prop192_csr() {
    int tid = threadIdx.x;
    int g = tid >> 4;
    int j = tid & 15;
    int d = blockIdx.x * 16 + g;
    if (d >= Nn) return;
    int c = 4*j;
    int beg = g_rowptr[d], end = g_rowptr[d+1];

    float sn = g_selfn[d];
    float4 a0 = *(const float4*)(g_xT + d*FT + c);
    float4 a1 = *(const float4*)(g_xT + d*FT + c + 64);
    float4 a2 = *(const float4*)(g_xT + d*FT + c + 128);
    float4 acc0, acc1, acc2;
    acc0.x = sn*a0.x; acc0.y = sn*a0.y; acc0.z = sn*a0.z; acc0.w = sn*a0.w;
    acc1.x = sn*a1.x; acc1.y = sn*a1.y; acc1.z = sn*a1.z; acc1.w = sn*a1.w;
    acc2.x = sn*a2.x; acc2.y = sn*a2.y; acc2.z = sn*a2.z; acc2.w = sn*a2.w;

    int e = beg;
    for (; e + 2 <= end; e += 2) {
        int   s0 = g_csrc[e],   s1 = g_csrc[e+1];
        float w0 = g_cw[e],     w1 = g_cw[e+1];
        const float* r0 = g_xT + s0*FT + c;
        const float* r1 = g_xT + s1*FT + c;
        float4 u0 = *(const float4*)(r0);
        float4 u1 = *(const float4*)(r0 + 64);
        float4 u2 = *(const float4*)(r0 + 128);
        float4 v0 = *(const float4*)(r1);
        float4 v1 = *(const float4*)(r1 + 64);
        float4 v2 = *(const float4*)(r1 + 128);
        acc0.x += w0*u0.x; acc0.y += w0*u0.y; acc0.z += w0*u0.z; acc0.w += w0*u0.w;
        acc1.x += w0*u1.x; acc1.y += w0*u1.y; acc1.z += w0*u1.z; acc1.w += w0*u1.w;
        acc2.x += w0*u2.x; acc2.y += w0*u2.y; acc2.z += w0*u2.z; acc2.w += w0*u2.w;
        acc0.x += w1*v0.x; acc0.y += w1*v0.y; acc0.z += w1*v0.z; acc0.w += w1*v0.w;
        acc1.x += w1*v1.x; acc1.y += w1*v1.y; acc1.z += w1*v1.z; acc1.w += w1*v1.w;
        acc2.x += w1*v2.x; acc2.y += w1*v2.y; acc2.z += w1*v2.z; acc2.w += w1*v2.w;
    }
    for (; e < end; e++) {
        int s = g_csrc[e]; float w = g_cw[e];
        const float* r = g_xT + s*FT + c;
        float4 u0 = *(const float4*)(r);
        float4 u1 = *(const float4*)(r + 64);
        float4 u2 = *(const float4*)(r + 128);
        acc0.x += w*u0.x; acc0.y += w*u0.y; acc0.z += w*u0.z; acc0.w += w*u0.w;
        acc1.x += w*u1.x; acc1.y += w*u1.y; acc1.z += w*u1.z; acc1.w += w*u1.w;
        acc2.x += w*u2.x; acc2.y += w*u2.y; acc2.z += w*u2.z; acc2.w += w*u2.w;
    }
    *(float4*)(g_Px + d*FT + c)       = acc0;
    *(float4*)(g_Px + d*FT + c + 64)  = acc1;
    *(float4*)(g_Px + d*FT + c + 128) = acc2;
}

// ---------------- GRU gate kernels -------------------------------------------
// z,r = sigmoid([Px_t, Ph] @ [Wz|Wr] + [bz|br]); also rh = r*h
__global__ __launch_bounds__(256) void k_gates(
    const float* __restrict__ Wz, const float* __restrict__ bz,
    const float* __restrict__ Wr, const float* __restrict__ br, int t)
{
    __shared__ float xin[16*80];
    __shared__ float Wsh[80*128];
    __shared__ float bsh[128];
    int tid = threadIdx.x;
    int nb = blockIdx.x * 16;

    for (int i = tid; i < 80*128; i += 256) {
        int k = i >> 7, c = i & 127;
        Wsh[i] = (c < 64) ? Wz[k*64 + c] : Wr[k*64 + (c - 64)];
    }
    if (tid < 128) bsh[tid] = (tid < 64) ? bz[tid] : br[tid - 64];
    for (int i = tid; i < 16*80; i += 256) {
        int nl = i / 80, k = i - nl*80;
        int n = nb + nl;
        xin[i] = (k < Ff) ? g_Px[n*FT + t*Ff + k] : g_Ph[n*Hh + (k - Ff)];
    }
    __syncthreads();

    int col4 = (tid & 31) * 4;   // 0..124
    int nr   = tid >> 5;         // 0..7
    float acc[2][4];
    #pragma unroll
    for (int i = 0; i < 2; i++)
        #pragma unroll
        for (int q = 0; q < 4; q++) acc[i][q] = bsh[col4 + q];

    #pragma unroll 4
    for (int k = 0; k < 80; k++) {
        float4 wv = *(const float4*)&Wsh[k*128 + col4];
        float x0 = xin[(nr*2 + 0)*80 + k];
        float x1 = xin[(nr*2 + 1)*80 + k];
        acc[0][0] += x0*wv.x; acc[0][1] += x0*wv.y; acc[0][2] += x0*wv.z; acc[0][3] += x0*wv.w;
        acc[1][0] += x1*wv.x; acc[1][1] += x1*wv.y; acc[1][2] += x1*wv.z; acc[1][3] += x1*wv.w;
    }

    #pragma unroll
    for (int i = 0; i < 2; i++) {
        int n = nb + nr*2 + i;
        float4 sv;
        sv.x = fsigmoid(acc[i][0]); sv.y = fsigmoid(acc[i][1]);
        sv.z = fsigmoid(acc[i][2]); sv.w = fsigmoid(acc[i][3]);
        if (col4 < 64) {
            *(float4*)&g_z[n*Hh + col4] = sv;
        } else {
            int c = col4 - 64;
            float4 hv = *(const float4*)&g_h[n*Hh + c];
            float4 rh; rh.x = sv.x*hv.x; rh.y = sv.y*hv.y; rh.z = sv.z*hv.z; rh.w = sv.w*hv.w;
            *(float4*)&g_rh[n*Hh + c] = rh;
        }
    }
}

// hc = tanh([Px_t, Prh] @ Wh + bh); h = z*h + (1-z)*hc; store hs
__global__ __launch_bounds__(256) void k_final(
    const float* __restrict__ Wh, const float* __restrict__ bh, int t)
{
    __shared__ float xin[32*80];
    __shared__ float Wsh[80*64];
    __shared__ float bsh[64];
    int tid = threadIdx.x;
    int nb = blockIdx.x * 32;

    for (int i = tid; i < 80*64; i += 256) Wsh[i] = Wh[i];
    if (tid < 64) bsh[tid] = bh[tid];
    for (int i = tid; i < 32*80; i += 256) {
        int nl = i / 80, k = i - nl*80;
        int n = nb + nl;
        float v = 0.f;
        if (n < Nn) v = (k < Ff) ? g_Px[n*FT + t*Ff + k] : g_Prh[n*Hh + (k - Ff)];
        xin[i] = v;
    }
    __syncthreads();

    int col4 = (tid & 15) * 4;   // 0..60
    int nr   = tid >> 4;         // 0..15
    float acc[2][4];
    #pragma unroll
    for (int i = 0; i < 2; i++)
        #pragma unroll
        for (int q = 0; q < 4; q++) acc[i][q] = bsh[col4 + q];

    #pragma unroll 4
    for (int k = 0; k < 80; k++) {
        float4 wv = *(const float4*)&Wsh[k*64 + col4];
        float x0 = xin[(nr*2 + 0)*80 + k];
        float x1 = xin[(nr*2 + 1)*80 + k];
        acc[0][0] += x0*wv.x; acc[0][1] += x0*wv.y; acc[0][2] += x0*wv.z; acc[0][3] += x0*wv.w;
        acc[1][0] += x1*wv.x; acc[1][1] += x1*wv.y; acc[1][2] += x1*wv.z; acc[1][3] += x1*wv.w;
    }

    #pragma unroll
    for (int i = 0; i < 2; i++) {
        int n = nb + nr*2 + i;
        if (n >= Nn) continue;
        float4 zv = *(const float4*)&g_z[n*Hh + col4];
        float4 hv = *(const float4*)&g_h[n*Hh + col4];
        float4 hn;
        hn.x = zv.x*hv.x + (1.f - zv.x)*ftanh(acc[i][0]);
        hn.y = zv.y*hv.y + (1.f - zv.y)*ftanh(acc[i][1]);
        hn.z = zv.z*hv.z + (1.f - zv.z)*ftanh(acc[i][2]);
        hn.w = zv.w*hv.w + (1.f - zv.w)*ftanh(acc[i][3]);
        *(float4*)&g_h[n*Hh + col4] = hn;
        *(float4*)&g_hs[n*(Tt*Hh) + t*Hh + col4] = hn;
    }
}

// ---------------- temporal attention + FC ------------------------------------
__global__ __launch_bounds__(256) void k_attn(
    const float* __restrict__ Wa, const float* __restrict__ ba,
    const float* __restrict__ cv, const float* __restrict__ Wfc,
    const float* __restrict__ bfc, float* __restrict__ out)
{
    __shared__ float Wa_sh[64*64];
    __shared__ float hs_sh[4][Tt*64];
    __shared__ float part[4][64*Tt];
    __shared__ float al_sh[4][Tt];
    __shared__ float cv_sh[64], ba_sh[64], Wfc_sh[64];
    __shared__ float redbuf[4][2];

    int tid = threadIdx.x;
    int nl  = tid >> 6;
    int j   = tid & 63;
    int n   = blockIdx.x * 4 + nl;
    bool valid = n < Nn;

    for (int i = tid; i < 4096; i += 256) Wa_sh[i] = Wa[i];
    if (tid < 64) { cv_sh[tid] = cv[tid]; ba_sh[tid] = ba[tid]; Wfc_sh[tid] = Wfc[tid]; }
    #pragma unroll
    for (int t = 0; t < Tt; t++)
        hs_sh[nl][t*64 + j] = valid ? g_hs[n*(Tt*Hh) + t*Hh + j] : 0.f;
    __syncthreads();

    #pragma unroll
    for (int t = 0; t < Tt; t++) {
        float acc = ba_sh[j];
        #pragma unroll 8
        for (int k = 0; k < 64; k++)
            acc += hs_sh[nl][t*64 + k] * Wa_sh[k*64 + j];
        part[nl][j*Tt + t] = ftanh(acc) * cv_sh[j];
    }
    __syncthreads();

    if (j < Tt) {
        float s = 0.f;
        #pragma unroll
        for (int q = 0; q < 64; q++) s += part[nl][q*Tt + j];
        al_sh[nl][j] = s;
    }
    __syncthreads();

    if (j == 0) {
        float m = -1e30f;
        #pragma unroll
        for (int t = 0; t < Tt; t++) m = fmaxf(m, al_sh[nl][t]);
        float e[Tt], ssum = 0.f;
        #pragma unroll
        for (int t = 0; t < Tt; t++) { e[t] = __expf(al_sh[nl][t] - m); ssum += e[t]; }
        float inv = 1.f / ssum;
        #pragma unroll
        for (int t = 0; t < Tt; t++) al_sh[nl][t] = e[t] * inv;
    }
    __syncthreads();

    float ctx = 0.f;
    #pragma unroll
    for (int t = 0; t < Tt; t++) ctx += al_sh[nl][t] * hs_sh[nl][t*64 + j];
    float o = ctx * Wfc_sh[j];
    #pragma unroll
    for (int off = 16; off; off >>= 1) o += __shfl_down_sync(0xffffffffu, o, off);
    if ((tid & 31) == 0) redbuf[nl][(tid >> 5) & 1] = o;
    __syncthreads();
    if (j == 0 && valid) out[n] = redbuf[nl][0] + redbuf[nl][1] + bfc[0];
}

// ---------------- launch ------------------------------------------------------
extern "C" void kernel_launch(void* const* d_in, const int* in_sizes, int n_in,
                              void* d_out, int out_size) {
    const float* x   = (const float*)d_in[0];
    const int*   ei  = (const int*)  d_in[1];
    const float* ew  = (const float*)d_in[2];
    const float* Wz  = (const float*)d_in[3];
    const float* bz  = (const float*)d_in[4];
    const float* Wr  = (const float*)d_in[5];
    const float* br  = (const float*)d_in[6];
    const float* Wh  = (const float*)d_in[7];
    const float* bh  = (const float*)d_in[8];
    const float* Wa  = (const float*)d_in[9];
    const float* ba  = (const float*)d_in[10];
    const float* cv  = (const float*)d_in[11];
    const float* Wfc = (const float*)d_in[12];
    const float* bfc = (const float*)d_in[13];
    float* out = (float*)d_out;

    k_init<<<(Nn*Hh + 255)/256, 256>>>();
    k_deg <<<(Ee + 255)/256, 256>>>(ei, ew);
    k_norm<<<(Nn + 255)/256, 256>>>();
    k_ewn <<<(Ee + 255)/256, 256>>>(ei, ew);
    k_scan<<<1, SCAN_TPB>>>();
    k_scatter<<<(Ee + 255)/256, 256>>>(ei);
    k_xT  <<<(Nn*FT + 255)/256, 256>>>(x);

    const int nodeBlocks = (Nn + 15)/16;  // 3125
    k_prop192_csr<<<nodeBlocks, 256>>>();

    for (int t = 0; t < Tt; t++) {
        if (t > 0) k_prop64_csr<<<nodeBlocks, 256>>>(0);   // h -> Ph
        k_gates<<<Nn/16, 256>>>(Wz, bz, Wr, br, t);        // z, r, rh
        if (t > 0) k_prop64_csr<<<nodeBlocks, 256>>>(1);   // rh -> Prh
        k_final<<<(Nn + 31)/32, 256>>>(Wh, bh, t);         // hc, h, hs
    }

    k_attn<<<(Nn + 3)/4, 256>>>(Wa, ba, cv, Wfc, bfc, out);
}

// round 6
// speedup vs baseline: 1.7673x; 1.1437x over previous
#include <cuda_runtime.h>
#include <cuda_fp16.h>

#define Nn 50000
#define Ff 16
#define Tt 12
#define Hh 64
#define Ee 1600000
#define FT (Ff*Tt)   // 192
#define SCAN_TPB 1024

// ---------------- scratch (static device globals; allocation-free) -----------
__device__ float g_deg[Nn];
__device__ float g_dis[Nn];
__device__ float g_selfn[Nn];
__device__ float g_ewn[Ee];
__device__ int   g_cnt[Nn];
__device__ int   g_rowptr[Nn+1];
__device__ int   g_off[Nn];
__device__ int2  g_epk[Ee];                         // packed {src, w-bits}
__device__ __align__(16) __half g_xTh[Nn*FT];       // x transposed, half, [N][T][F]
__device__ float g_Px[Nn*FT];                       // A_hat @ x (fp32)
__device__ float g_h[Nn*Hh];                        // master state fp32
__device__ __align__(16) __half g_hH[Nn*Hh];        // gather copy of h
__device__ __align__(16) __half g_rhH[Nn*Hh];       // gather copy of r*h
__device__ float g_Ph[Nn*Hh];
__device__ float g_z[Nn*Hh];
__device__ float g_Prh[Nn*Hh];
__device__ float g_hs[Nn*Tt*Hh];

// ---------------- helpers ----------------------------------------------------
__device__ __forceinline__ float fsigmoid(float x) { return 1.f / (1.f + __expf(-x)); }
__device__ __forceinline__ float ftanh(float x)    { return 1.f - 2.f / (__expf(2.f*x) + 1.f); }

__device__ __forceinline__ void cvt8(const uint4 raw, float f[8]) {
    float2 a = __half22float2(*(const __half2*)&raw.x);
    float2 b = __half22float2(*(const __half2*)&raw.y);
    float2 c = __half22float2(*(const __half2*)&raw.z);
    float2 d = __half22float2(*(const __half2*)&raw.w);
    f[0]=a.x; f[1]=a.y; f[2]=b.x; f[3]=b.y; f[4]=c.x; f[5]=c.y; f[6]=d.x; f[7]=d.y;
}

// ---------------- setup kernels ----------------------------------------------
__global__ void k_init() {
    int i = blockIdx.x * blockDim.x + threadIdx.x;
    if (i < Nn) { g_deg[i] = 1.f; g_cnt[i] = 0; }
    if (i < Nn*Hh) {
        g_h[i] = 0.f;
        g_hH[i] = __float2half(0.f);
        g_Ph[i] = 0.f;      // read at t=0 (prop skipped since h==0) — must be zero EVERY call
        g_Prh[i] = 0.f;     // ditto
    }
}

__global__ void k_deg(const int* __restrict__ ei, const float* __restrict__ w) {
    int e = blockIdx.x * blockDim.x + threadIdx.x;
    if (e < Ee) {
        int d = ei[Ee + e];
        atomicAdd(&g_deg[d], w[e]);
        atomicAdd(&g_cnt[d], 1);
    }
}

__global__ void k_norm() {
    int i = blockIdx.x * blockDim.x + threadIdx.x;
    if (i < Nn) { float d = g_deg[i]; g_dis[i] = rsqrtf(d); g_selfn[i] = 1.f / d; }
}

__global__ void k_ewn(const int* __restrict__ ei, const float* __restrict__ w) {
    int e = blockIdx.x * blockDim.x + threadIdx.x;
    if (e < Ee) g_ewn[e] = g_dis[ei[e]] * w[e] * g_dis[ei[Ee + e]];
}

__global__ __launch_bounds__(SCAN_TPB) void k_scan() {
    __shared__ int sh[SCAN_TPB];
    const int CH = (Nn + SCAN_TPB - 1) / SCAN_TPB;
    int t = threadIdx.x;
    int base = t * CH;
    int sum = 0;
    for (int i = 0; i < CH; i++) { int idx = base + i; if (idx < Nn) sum += g_cnt[idx]; }
    sh[t] = sum;
    __syncthreads();
    for (int off = 1; off < SCAN_TPB; off <<= 1) {
        int v = (t >= off) ? sh[t - off] : 0;
        __syncthreads();
        sh[t] += v;
        __syncthreads();
    }
    int run = (t > 0) ? sh[t - 1] : 0;
    for (int i = 0; i < CH; i++) {
        int idx = base + i;
        if (idx < Nn) { int c = g_cnt[idx]; g_rowptr[idx] = run; g_off[idx] = run; run += c; }
    }
    if (t == SCAN_TPB - 1) g_rowptr[Nn] = run;
}

__global__ void k_scatter(const int* __restrict__ ei) {
    int e = blockIdx.x * blockDim.x + threadIdx.x;
    if (e < Ee) {
        int d = ei[Ee + e];
        int pos = atomicAdd(&g_off[d], 1);
        g_epk[pos] = make_int2(ei[e], __float_as_int(g_ewn[e]));
    }
}

// transpose x [N][F][T] -> xTh [N][T][F] (half)
__global__ void k_xT(const float* __restrict__ x) {
    int i = blockIdx.x * blockDim.x + threadIdx.x;
    if (i >= Nn*FT) return;
    int n = i / FT, r = i % FT, f = r / Tt, t = r % Tt;
    g_xTh[n*FT + t*Ff + f] = __float2half(x[i]);
}

// ---------------- CSR pull-mode propagation (half gathers) --------------------
// which=0: hH->Ph, which=1: rhH->Prh. 8 threads per dst node, 32 nodes/block.
__global__ __launch_bounds__(256) void k_prop64_csr(int which) {
    const __half* __restrict__ X = which ? g_rhH : g_hH;
    float*        __restrict__ Y = which ? g_Prh : g_Ph;
    int tid = threadIdx.x;
    int g = tid >> 3;
    int j = tid & 7;
    int d = blockIdx.x * 32 + g;
    if (d >= Nn) return;
    int c = 8*j;
    int beg = g_rowptr[d], end = g_rowptr[d+1];

    float sn = g_selfn[d];
    float acc[8];
    {
        uint4 raw = *(const uint4*)(X + d*Hh + c);
        float f[8]; cvt8(raw, f);
        #pragma unroll
        for (int q = 0; q < 8; q++) acc[q] = sn * f[q];
    }

    int e = beg;
    for (; e + 4 <= end; e += 4) {
        int2 p0 = g_epk[e], p1 = g_epk[e+1], p2 = g_epk[e+2], p3 = g_epk[e+3];
        uint4 r0 = *(const uint4*)(X + p0.x*Hh + c);
        uint4 r1 = *(const uint4*)(X + p1.x*Hh + c);
        uint4 r2 = *(const uint4*)(X + p2.x*Hh + c);
        uint4 r3 = *(const uint4*)(X + p3.x*Hh + c);
        float w0 = __int_as_float(p0.y), w1 = __int_as_float(p1.y);
        float w2 = __int_as_float(p2.y), w3 = __int_as_float(p3.y);
        float f[8];
        cvt8(r0, f);
        #pragma unroll
        for (int q = 0; q < 8; q++) acc[q] += w0 * f[q];
        cvt8(r1, f);
        #pragma unroll
        for (int q = 0; q < 8; q++) acc[q] += w1 * f[q];
        cvt8(r2, f);
        #pragma unroll
        for (int q = 0; q < 8; q++) acc[q] += w2 * f[q];
        cvt8(r3, f);
        #pragma unroll
        for (int q = 0; q < 8; q++) acc[q] += w3 * f[q];
    }
    for (; e < end; e++) {
        int2 p = g_epk[e];
        uint4 r = *(const uint4*)(X + p.x*Hh + c);
        float w = __int_as_float(p.y);
        float f[8]; cvt8(r, f);
        #pragma unroll
        for (int q = 0; q < 8; q++) acc[q] += w * f[q];
    }

    float4 o0 = {acc[0], acc[1], acc[2], acc[3]};
    float4 o1 = {acc[4], acc[5], acc[6], acc[7]};
    *(float4*)(Y + d*Hh + c)     = o0;
    *(float4*)(Y + d*Hh + c + 4) = o1;
}

// 192-col version: xTh -> Px, 3 chunks of 8 halves per thread
__global__ __launch_bounds__(256) void k_prop192_csr() {
    int tid = threadIdx.x;
    int g = tid >> 3;
    int j = tid & 7;
    int d = blockIdx.x * 32 + g;
    if (d >= Nn) return;
    int c = 8*j;
    int beg = g_rowptr[d], end = g_rowptr[d+1];

    float sn = g_selfn[d];
    float acc[3][8];
    {
        const __half* r = g_xTh + d*FT + c;
        #pragma unroll
        for (int ch = 0; ch < 3; ch++) {
            uint4 raw = *(const uint4*)(r + 64*ch);
            float f[8]; cvt8(raw, f);
            #pragma unroll
            for (int q = 0; q < 8; q++) acc[ch][q] = sn * f[q];
        }
    }

    int e = beg;
    for (; e + 2 <= end; e += 2) {
        int2 p0 = g_epk[e], p1 = g_epk[e+1];
        const __half* r0 = g_xTh + p0.x*FT + c;
        const __half* r1 = g_xTh + p1.x*FT + c;
        uint4 a0 = *(const uint4*)(r0);
        uint4 a1 = *(const uint4*)(r0 + 64);
        uint4 a2 = *(const uint4*)(r0 + 128);
        uint4 b0 = *(const uint4*)(r1);
        uint4 b1 = *(const uint4*)(r1 + 64);
        uint4 b2 = *(const uint4*)(r1 + 128);
        float w0 = __int_as_float(p0.y), w1 = __int_as_float(p1.y);
        float f[8];
        cvt8(a0, f);
        #pragma unroll
        for (int q = 0; q < 8; q++) acc[0][q] += w0 * f[q];
        cvt8(a1, f);
        #pragma unroll
        for (int q = 0; q < 8; q++) acc[1][q] += w0 * f[q];
        cvt8(a2, f);
        #pragma unroll
        for (int q = 0; q < 8; q++) acc[2][q] += w0 * f[q];
        cvt8(b0, f);
        #pragma unroll
        for (int q = 0; q < 8; q++) acc[0][q] += w1 * f[q];
        cvt8(b1, f);
        #pragma unroll
        for (int q = 0; q < 8; q++) acc[1][q] += w1 * f[q];
        cvt8(b2, f);
        #pragma unroll
        for (int q = 0; q < 8; q++) acc[2][q] += w1 * f[q];
    }
    for (; e < end; e++) {
        int2 p = g_epk[e];
        const __half* r = g_xTh + p.x*FT + c;
        float w = __int_as_float(p.y);
        #pragma unroll
        for (int ch = 0; ch < 3; ch++) {
            uint4 raw = *(const uint4*)(r + 64*ch);
            float f[8]; cvt8(raw, f);
            #pragma unroll
            for (int q = 0; q < 8; q++) acc[ch][q] += w * f[q];
        }
    }

    #pragma unroll
    for (int ch = 0; ch < 3; ch++) {
        float4 o0 = {acc[ch][0], acc[ch][1], acc[ch][2], acc[ch][3]};
        float4 o1 = {acc[ch][4], acc[ch][5], acc[ch][6], acc[ch][7]};
        *(float4*)(g_Px + d*FT + c + 64*ch)     = o0;
        *(float4*)(g_Px + d*FT + c + 64*ch + 4) = o1;
    }
}

// ---------------- GRU gate kernels -------------------------------------------
// z,r = sigmoid([Px_t, Ph] @ [Wz|Wr] + [bz|br]); also rhH = half(r*h)
// 32 nodes per block.
__global__ __launch_bounds__(256) void k_gates(
    const float* __restrict__ Wz, const float* __restrict__ bz,
    const float* __restrict__ Wr, const float* __restrict__ br, int t)
{
    __shared__ float xin[32*80];    // 10KB
    __shared__ float Wsh[80*128];   // 40KB
    __shared__ float bsh[128];
    int tid = threadIdx.x;
    int nb = blockIdx.x * 32;

    for (int i = tid; i < 80*128; i += 256) {
        int k = i >> 7, c = i & 127;
        Wsh[i] = (c < 64) ? Wz[k*64 + c] : Wr[k*64 + (c - 64)];
    }
    if (tid < 128) bsh[tid] = (tid < 64) ? bz[tid] : br[tid - 64];
    for (int i = tid; i < 32*80; i += 256) {
        int nl = i / 80, k = i - nl*80;
        int n = nb + nl;
        float v = 0.f;
        if (n < Nn) v = (k < Ff) ? g_Px[n*FT + t*Ff + k] : g_Ph[n*Hh + (k - Ff)];
        xin[i] = v;
    }
    __syncthreads();

    int col4 = (tid & 31) * 4;   // 0..124
    int nr   = tid >> 5;         // 0..7 -> 4 nodes each
    float acc[4][4];
    #pragma unroll
    for (int i = 0; i < 4; i++)
        #pragma unroll
        for (int q = 0; q < 4; q++) acc[i][q] = bsh[col4 + q];

    #pragma unroll 4
    for (int k = 0; k < 80; k++) {
        float4 wv = *(const float4*)&Wsh[k*128 + col4];
        #pragma unroll
        for (int i = 0; i < 4; i++) {
            float xv = xin[(nr*4 + i)*80 + k];
            acc[i][0] += xv*wv.x; acc[i][1] += xv*wv.y;
            acc[i][2] += xv*wv.z; acc[i][3] += xv*wv.w;
        }
    }

    #pragma unroll
    for (int i = 0; i < 4; i++) {
        int n = nb + nr*4 + i;
        if (n >= Nn) continue;
        float4 sv;
        sv.x = fsigmoid(acc[i][0]); sv.y = fsigmoid(acc[i][1]);
        sv.z = fsigmoid(acc[i][2]); sv.w = fsigmoid(acc[i][3]);
        if (col4 < 64) {
            *(float4*)&g_z[n*Hh + col4] = sv;
        } else {
            int c = col4 - 64;
            float4 hv = *(const float4*)&g_h[n*Hh + c];
            __half2 p0 = __floats2half2_rn(sv.x*hv.x, sv.y*hv.y);
            __half2 p1 = __floats2half2_rn(sv.z*hv.z, sv.w*hv.w);
            *(__half2*)&g_rhH[n*Hh + c]     = p0;
            *(__half2*)&g_rhH[n*Hh + c + 2] = p1;
        }
    }
}

// hc = tanh([Px_t, Prh] @ Wh + bh); h = z*h + (1-z)*hc; store hs + hH
// 64 nodes per block.
__global__ __launch_bounds__(256) void k_final(
    const float* __restrict__ Wh, const float* __restrict__ bh, int t)
{
    __shared__ float xin[64*80];   // 20KB
    __shared__ float Wsh[80*64];   // 20KB
    __shared__ float bsh[64];
    int tid = threadIdx.x;
    int nb = blockIdx.x * 64;

    for (int i = tid; i < 80*64; i += 256) Wsh[i] = Wh[i];
    if (tid < 64) bsh[tid] = bh[tid];
    for (int i = tid; i < 64*80; i += 256) {
        int nl = i / 80, k = i - nl*80;
        int n = nb + nl;
        float v = 0.f;
        if (n < Nn) v = (k < Ff) ? g_Px[n*FT + t*Ff + k] : g_Prh[n*Hh + (k - Ff)];
        xin[i] = v;
    }
    __syncthreads();

    int col4 = (tid & 15) * 4;   // 0..60
    int nr   = tid >> 4;         // 0..15 -> 4 nodes each
    float acc[4][4];
    #pragma unroll
    for (int i = 0; i < 4; i++)
        #pragma unroll
        for (int q = 0; q < 4; q++) acc[i][q] = bsh[col4 + q];

    #pragma unroll 4
    for (int k = 0; k < 80; k++) {
        float4 wv = *(const float4*)&Wsh[k*64 + col4];
        #pragma unroll
        for (int i = 0; i < 4; i++) {
            float xv = xin[(nr*4 + i)*80 + k];
            acc[i][0] += xv*wv.x; acc[i][1] += xv*wv.y;
            acc[i][2] += xv*wv.z; acc[i][3] += xv*wv.w;
        }
    }

    #pragma unroll
    for (int i = 0; i < 4; i++) {
        int n = nb + nr*4 + i;
        if (n >= Nn) continue;
        float4 zv = *(const float4*)&g_z[n*Hh + col4];
        float4 hv = *(const float4*)&g_h[n*Hh + col4];
        float4 hn;
        hn.x = zv.x*hv.x + (1.f - zv.x)*ftanh(acc[i][0]);
        hn.y = zv.y*hv.y + (1.f - zv.y)*ftanh(acc[i][1]);
        hn.z = zv.z*hv.z + (1.f - zv.z)*ftanh(acc[i][2]);
        hn.w = zv.w*hv.w + (1.f - zv.w)*ftanh(acc[i][3]);
        *(float4*)&g_h[n*Hh + col4] = hn;
        *(float4*)&g_hs[n*(Tt*Hh) + t*Hh + col4] = hn;
        __half2 p0 = __floats2half2_rn(hn.x, hn.y);
        __half2 p1 = __floats2half2_rn(hn.z, hn.w);
        *(__half2*)&g_hH[n*Hh + col4]     = p0;
        *(__half2*)&g_hH[n*Hh + col4 + 2] = p1;
    }
}

// ---------------- temporal attention + FC ------------------------------------
__global__ __launch_bounds__(256) void k_attn(
    const float* __restrict__ Wa, const float* __restrict__ ba,
    const float* __restrict__ cv, const float* __restrict__ Wfc,
    const float* __restrict__ bfc, float* __restrict__ out)
{
    __shared__ float Wa_sh[64*64];
    __shared__ float hs_sh[4][Tt*64];
    __shared__ float part[4][64*Tt];
    __shared__ float al_sh[4][Tt];
    __shared__ float cv_sh[64], ba_sh[64], Wfc_sh[64];
    __shared__ float redbuf[4][2];

    int tid = threadIdx.x;
    int nl  = tid >> 6;
    int j   = tid & 63;
    int n   = blockIdx.x * 4 + nl;
    bool valid = n < Nn;

    for (int i = tid; i < 4096; i += 256) Wa_sh[i] = Wa[i];
    if (tid < 64) { cv_sh[tid] = cv[tid]; ba_sh[tid] = ba[tid]; Wfc_sh[tid] = Wfc[tid]; }
    #pragma unroll
    for (int t = 0; t < Tt; t++)
        hs_sh[nl][t*64 + j] = valid ? g_hs[n*(Tt*Hh) + t*Hh + j] : 0.f;
    __syncthreads();

    #pragma unroll
    for (int t = 0; t < Tt; t++) {
        float acc = ba_sh[j];
        #pragma unroll 8
        for (int k = 0; k < 64; k++)
            acc += hs_sh[nl][t*64 + k] * Wa_sh[k*64 + j];
        part[nl][j*Tt + t] = ftanh(acc) * cv_sh[j];
    }
    __syncthreads();

    if (j < Tt) {
        float s = 0.f;
        #pragma unroll
        for (int q = 0; q < 64; q++) s += part[nl][q*Tt + j];
        al_sh[nl][j] = s;
    }
    __syncthreads();

    if (j == 0) {
        float m = -1e30f;
        #pragma unroll
        for (int t = 0; t < Tt; t++) m = fmaxf(m, al_sh[nl][t]);
        float e[Tt], ssum = 0.f;
        #pragma unroll
        for (int t = 0; t < Tt; t++) { e[t] = __expf(al_sh[nl][t] - m); ssum += e[t]; }
        float inv = 1.f / ssum;
        #pragma unroll
        for (int t = 0; t < Tt; t++) al_sh[nl][t] = e[t] * inv;
    }
    __syncthreads();

    float ctx = 0.f;
    #pragma unroll
    for (int t = 0; t < Tt; t++) ctx += al_sh[nl][t] * hs_sh[nl][t*64 + j];
    float o = ctx * Wfc_sh[j];
    #pragma unroll
    for (int off = 16; off; off >>= 1) o += __shfl_down_sync(0xffffffffu, o, off);
    if ((tid & 31) == 0) redbuf[nl][(tid >> 5) & 1] = o;
    __syncthreads();
    if (j == 0 && valid) out[n] = redbuf[nl][0] + redbuf[nl][1] + bfc[0];
}

// ---------------- launch ------------------------------------------------------
extern "C" void kernel_launch(void* const* d_in, const int* in_sizes, int n_in,
                              void* d_out, int out_size) {
    const float* x   = (const float*)d_in[0];
    const int*   ei  = (const int*)  d_in[1];
    const float* ew  = (const float*)d_in[2];
    const float* Wz  = (const float*)d_in[3];
    const float* bz  = (const float*)d_in[4];
    const float* Wr  = (const float*)d_in[5];
    const float* br  = (const float*)d_in[6];
    const float* Wh  = (const float*)d_in[7];
    const float* bh  = (const float*)d_in[8];
    const float* Wa  = (const float*)d_in[9];
    const float* ba  = (const float*)d_in[10];
    const float* cv  = (const float*)d_in[11];
    const float* Wfc = (const float*)d_in[12];
    const float* bfc = (const float*)d_in[13];
    float* out = (float*)d_out;

    k_init<<<(Nn*Hh + 255)/256, 256>>>();
    k_deg <<<(Ee + 255)/256, 256>>>(ei, ew);
    k_norm<<<(Nn + 255)/256, 256>>>();
    k_ewn <<<(Ee + 255)/256, 256>>>(ei, ew);
    k_scan<<<1, SCAN_TPB>>>();
    k_scatter<<<(Ee + 255)/256, 256>>>(ei);
    k_xT  <<<(Nn*FT + 255)/256, 256>>>(x);

    const int propBlocks = (Nn + 31)/32;   // 1563
    k_prop192_csr<<<propBlocks, 256>>>();

    const int gateBlocks  = (Nn + 31)/32;  // 1563
    const int finalBlocks = (Nn + 63)/64;  // 782
    for (int t = 0; t < Tt; t++) {
        if (t > 0) k_prop64_csr<<<propBlocks, 256>>>(0);   // hH -> Ph
        k_gates<<<gateBlocks, 256>>>(Wz, bz, Wr, br, t);   // z, rhH
        if (t > 0) k_prop64_csr<<<propBlocks, 256>>>(1);   // rhH -> Prh
        k_final<<<finalBlocks, 256>>>(Wh, bh, t);          // h, hH, hs
    }

    k_attn<<<(Nn + 3)/4, 256>>>(Wa, ba, cv, Wfc, bfc, out);
}

// round 7
// speedup vs baseline: 2.2538x; 1.2753x over previous
#include <cuda_runtime.h>
#include <cuda_fp16.h>
#include <cstdint>

#define Nn 50000
#define Ff 16
#define Tt 12
#define Hh 64
#define Ee 1600000
#define FT 192
#define SCAN_TPB 1024

// ---------------- scratch (static device globals; allocation-free) -----------
__device__ float g_deg[Nn];
__device__ float g_dis[Nn];
__device__ float g_selfn[Nn];
__device__ float g_ewn[Ee];
__device__ int   g_cnt[Nn];
__device__ int   g_rowptr[Nn+1];
__device__ int   g_off[Nn];
__device__ int2  g_epk[Ee];                         // packed {src, w-bits}
__device__ __align__(16) __half g_xTh[Nn*FT];       // x transposed half [N][T][F]
__device__ __align__(16) __half g_PxH[Nn*FT];       // A_hat @ x, half
__device__ float g_h[Nn*Hh];                        // master state fp32
__device__ __align__(16) __half g_hH[Nn*Hh];        // gather copy of h
__device__ __align__(16) __half g_rhH[Nn*Hh];       // gather copy of r*h
__device__ __align__(16) __half g_PhH[Nn*Hh];       // A_hat @ h, half
__device__ __align__(16) __half g_PrhH[Nn*Hh];      // A_hat @ (r*h), half
__device__ float g_z[Nn*Hh];
__device__ float g_hs[Nn*Tt*Hh];
__device__ __align__(16) __half g_WzrT[128*80];     // [n][k], n<64: Wz, else Wr
__device__ __align__(16) __half g_WhT[64*80];       // [n][k]

// ---------------- helpers ----------------------------------------------------
__device__ __forceinline__ float fsigmoid(float x) { return 1.f / (1.f + __expf(-x)); }
__device__ __forceinline__ float ftanh(float x)    { return 1.f - 2.f / (__expf(2.f*x) + 1.f); }

__device__ __forceinline__ void cvt8(const uint4 raw, float f[8]) {
    float2 a = __half22float2(*(const __half2*)&raw.x);
    float2 b = __half22float2(*(const __half2*)&raw.y);
    float2 c = __half22float2(*(const __half2*)&raw.z);
    float2 d = __half22float2(*(const __half2*)&raw.w);
    f[0]=a.x; f[1]=a.y; f[2]=b.x; f[3]=b.y; f[4]=c.x; f[5]=c.y; f[6]=d.x; f[7]=d.y;
}

__device__ __forceinline__ uint32_t smemu32(const void* p) {
    return (uint32_t)__cvta_generic_to_shared(p);
}
__device__ __forceinline__ void ldmA4(uint32_t a[4], uint32_t addr) {
    asm volatile("ldmatrix.sync.aligned.m8n8.x4.shared.b16 {%0,%1,%2,%3}, [%4];"
        : "=r"(a[0]), "=r"(a[1]), "=r"(a[2]), "=r"(a[3]) : "r"(addr));
}
__device__ __forceinline__ void mma16816(float c[4], const uint32_t a[4],
                                         uint32_t b0, uint32_t b1) {
    asm volatile("mma.sync.aligned.m16n8k16.row.col.f32.f16.f16.f32 "
        "{%0,%1,%2,%3}, {%4,%5,%6,%7}, {%8,%9}, {%0,%1,%2,%3};"
        : "+f"(c[0]), "+f"(c[1]), "+f"(c[2]), "+f"(c[3])
        : "r"(a[0]), "r"(a[1]), "r"(a[2]), "r"(a[3]), "r"(b0), "r"(b1));
}

// ---------------- setup kernels ----------------------------------------------
__global__ void k_init() {
    int i = blockIdx.x * blockDim.x + threadIdx.x;
    if (i < Nn) { g_deg[i] = 1.f; g_cnt[i] = 0; }
    if (i < Nn*Hh) {
        g_h[i]    = 0.f;
        g_hH[i]   = __float2half(0.f);
        g_PhH[i]  = __float2half(0.f);   // read at t=0 every call
        g_PrhH[i] = __float2half(0.f);   // ditto
    }
}

__global__ void k_deg(const int* __restrict__ ei, const float* __restrict__ w) {
    int e = blockIdx.x * blockDim.x + threadIdx.x;
    if (e < Ee) {
        int d = ei[Ee + e];
        atomicAdd(&g_deg[d], w[e]);
        atomicAdd(&g_cnt[d], 1);
    }
}

__global__ void k_norm() {
    int i = blockIdx.x * blockDim.x + threadIdx.x;
    if (i < Nn) { float d = g_deg[i]; g_dis[i] = rsqrtf(d); g_selfn[i] = 1.f / d; }
}

__global__ void k_ewn(const int* __restrict__ ei, const float* __restrict__ w) {
    int e = blockIdx.x * blockDim.x + threadIdx.x;
    if (e < Ee) g_ewn[e] = g_dis[ei[e]] * w[e] * g_dis[ei[Ee + e]];
}

__global__ __launch_bounds__(SCAN_TPB) void k_scan() {
    __shared__ int sh[SCAN_TPB];
    const int CH = (Nn + SCAN_TPB - 1) / SCAN_TPB;
    int t = threadIdx.x;
    int base = t * CH;
    int sum = 0;
    for (int i = 0; i < CH; i++) { int idx = base + i; if (idx < Nn) sum += g_cnt[idx]; }
    sh[t] = sum;
    __syncthreads();
    for (int off = 1; off < SCAN_TPB; off <<= 1) {
        int v = (t >= off) ? sh[t - off] : 0;
        __syncthreads();
        sh[t] += v;
        __syncthreads();
    }
    int run = (t > 0) ? sh[t - 1] : 0;
    for (int i = 0; i < CH; i++) {
        int idx = base + i;
        if (idx < Nn) { int c = g_cnt[idx]; g_rowptr[idx] = run; g_off[idx] = run; run += c; }
    }
    if (t == SCAN_TPB - 1) g_rowptr[Nn] = run;
}

__global__ void k_scatter(const int* __restrict__ ei) {
    int e = blockIdx.x * blockDim.x + threadIdx.x;
    if (e < Ee) {
        int d = ei[Ee + e];
        int pos = atomicAdd(&g_off[d], 1);
        g_epk[pos] = make_int2(ei[e], __float_as_int(g_ewn[e]));
    }
}

// transpose x [N][F][T] -> xTh [N][T][F] (half)
__global__ void k_xT(const float* __restrict__ x) {
    int i = blockIdx.x * blockDim.x + threadIdx.x;
    if (i >= Nn*FT) return;
    int n = i / FT, r = i % FT, f = r / Tt, t = r % Tt;
    g_xTh[n*FT + t*Ff + f] = __float2half(x[i]);
}

// weights -> transposed half [N][K]
__global__ void k_wcvt(const float* __restrict__ Wz, const float* __restrict__ Wr,
                       const float* __restrict__ Wh) {
    int i = blockIdx.x * blockDim.x + threadIdx.x;
    if (i < 128*80) {
        int n = i / 80, k = i % 80;
        float v = (n < 64) ? Wz[k*64 + n] : Wr[k*64 + (n - 64)];
        g_WzrT[i] = __float2half(v);
    }
    if (i < 64*80) {
        int n = i / 80, k = i % 80;
        g_WhT[i] = __float2half(Wh[k*64 + n]);
    }
}

// ---------------- CSR pull-mode propagation (half gathers, half outputs) ------
__global__ __launch_bounds__(256) void k_prop64_csr(int which) {
    const __half* __restrict__ X = which ? g_rhH  : g_hH;
    __half*       __restrict__ Y = which ? g_PrhH : g_PhH;
    int tid = threadIdx.x;
    int g = tid >> 3;
    int j = tid & 7;
    int d = blockIdx.x * 32 + g;
    if (d >= Nn) return;
    int c = 8*j;
    int beg = g_rowptr[d], end = g_rowptr[d+1];

    float sn = g_selfn[d];
    float acc[8];
    {
        uint4 raw = *(const uint4*)(X + d*Hh + c);
        float f[8]; cvt8(raw, f);
        #pragma unroll
        for (int q = 0; q < 8; q++) acc[q] = sn * f[q];
    }

    int e = beg;
    for (; e + 4 <= end; e += 4) {
        int2 p0 = g_epk[e], p1 = g_epk[e+1], p2 = g_epk[e+2], p3 = g_epk[e+3];
        uint4 r0 = *(const uint4*)(X + p0.x*Hh + c);
        uint4 r1 = *(const uint4*)(X + p1.x*Hh + c);
        uint4 r2 = *(const uint4*)(X + p2.x*Hh + c);
        uint4 r3 = *(const uint4*)(X + p3.x*Hh + c);
        float w0 = __int_as_float(p0.y), w1 = __int_as_float(p1.y);
        float w2 = __int_as_float(p2.y), w3 = __int_as_float(p3.y);
        float f[8];
        cvt8(r0, f);
        #pragma unroll
        for (int q = 0; q < 8; q++) acc[q] += w0 * f[q];
        cvt8(r1, f);
        #pragma unroll
        for (int q = 0; q < 8; q++) acc[q] += w1 * f[q];
        cvt8(r2, f);
        #pragma unroll
        for (int q = 0; q < 8; q++) acc[q] += w2 * f[q];
        cvt8(r3, f);
        #pragma unroll
        for (int q = 0; q < 8; q++) acc[q] += w3 * f[q];
    }
    for (; e < end; e++) {
        int2 p = g_epk[e];
        uint4 r = *(const uint4*)(X + p.x*Hh + c);
        float w = __int_as_float(p.y);
        float f[8]; cvt8(r, f);
        #pragma unroll
        for (int q = 0; q < 8; q++) acc[q] += w * f[q];
    }

    uint4 pk;
    ((__half2*)&pk)[0] = __floats2half2_rn(acc[0], acc[1]);
    ((__half2*)&pk)[1] = __floats2half2_rn(acc[2], acc[3]);
    ((__half2*)&pk)[2] = __floats2half2_rn(acc[4], acc[5]);
    ((__half2*)&pk)[3] = __floats2half2_rn(acc[6], acc[7]);
    *(uint4*)(Y + d*Hh + c) = pk;
}

__global__ __launch_bounds__(256) void k_prop192_csr() {
    int tid = threadIdx.x;
    int g = tid >> 3;
    int j = tid & 7;
    int d = blockIdx.x * 32 + g;
    if (d >= Nn) return;
    int c = 8*j;
    int beg = g_rowptr[d], end = g_rowptr[d+1];

    float sn = g_selfn[d];
    float acc[3][8];
    {
        const __half* r = g_xTh + d*FT + c;
        #pragma unroll
        for (int ch = 0; ch < 3; ch++) {
            uint4 raw = *(const uint4*)(r + 64*ch);
            float f[8]; cvt8(raw, f);
            #pragma unroll
            for (int q = 0; q < 8; q++) acc[ch][q] = sn * f[q];
        }
    }

    int e = beg;
    for (; e + 2 <= end; e += 2) {
        int2 p0 = g_epk[e], p1 = g_epk[e+1];
        const __half* r0 = g_xTh + p0.x*FT + c;
        const __half* r1 = g_xTh + p1.x*FT + c;
        uint4 a0 = *(const uint4*)(r0);
        uint4 a1 = *(const uint4*)(r0 + 64);
        uint4 a2 = *(const uint4*)(r0 + 128);
        uint4 b0 = *(const uint4*)(r1);
        uint4 b1 = *(const uint4*)(r1 + 64);
        uint4 b2 = *(const uint4*)(r1 + 128);
        float w0 = __int_as_float(p0.y), w1 = __int_as_float(p1.y);
        float f[8];
        cvt8(a0, f);
        #pragma unroll
        for (int q = 0; q < 8; q++) acc[0][q] += w0 * f[q];
        cvt8(a1, f);
        #pragma unroll
        for (int q = 0; q < 8; q++) acc[1][q] += w0 * f[q];
        cvt8(a2, f);
        #pragma unroll
        for (int q = 0; q < 8; q++) acc[2][q] += w0 * f[q];
        cvt8(b0, f);
        #pragma unroll
        for (int q = 0; q < 8; q++) acc[0][q] += w1 * f[q];
        cvt8(b1, f);
        #pragma unroll
        for (int q = 0; q < 8; q++) acc[1][q] += w1 * f[q];
        cvt8(b2, f);
        #pragma unroll
        for (int q = 0; q < 8; q++) acc[2][q] += w1 * f[q];
    }
    for (; e < end; e++) {
        int2 p = g_epk[e];
        const __half* r = g_xTh + p.x*FT + c;
        float w = __int_as_float(p.y);
        #pragma unroll
        for (int ch = 0; ch < 3; ch++) {
            uint4 raw = *(const uint4*)(r + 64*ch);
            float f[8]; cvt8(raw, f);
            #pragma unroll
            for (int q = 0; q < 8; q++) acc[ch][q] += w * f[q];
        }
    }

    #pragma unroll
    for (int ch = 0; ch < 3; ch++) {
        uint4 pk;
        ((__half2*)&pk)[0] = __floats2half2_rn(acc[ch][0], acc[ch][1]);
        ((__half2*)&pk)[1] = __floats2half2_rn(acc[ch][2], acc[ch][3]);
        ((__half2*)&pk)[2] = __floats2half2_rn(acc[ch][4], acc[ch][5]);
        ((__half2*)&pk)[3] = __floats2half2_rn(acc[ch][6], acc[ch][7]);
        *(uint4*)(g_PxH + d*FT + c + 64*ch) = pk;
    }
}

// ---------------- tensor-core GRU gate kernels --------------------------------
// gates: [Px_t | Ph] (128 nodes x 80) @ [Wz|Wr]^T (128x80) -> z (fp32), rhH (half)
// 8 warps: wm 0..3 (m32 each), wn 0..1 (n64 each).
__global__ __launch_bounds__(256) void k_gates_mma(
    const float* __restrict__ bz, const float* __restrict__ br, int t)
{
    __shared__ __half Ash[128*88];   // 22528 B
    __shared__ __half Wsh[128*88];   // 22528 B
    __shared__ float  bsh[128];
    int tid = threadIdx.x;
    int lane = tid & 31, w = tid >> 5;
    int wm = w & 3, wn = w >> 2;
    int nb = blockIdx.x * 128;

    if (tid < 128) bsh[tid] = (tid < 64) ? bz[tid] : br[tid - 64];
    for (int i = tid; i < 128*10; i += 256) {
        int n = i / 10, q = i % 10;
        *(uint4*)&Wsh[n*88 + q*8] = *(const uint4*)&g_WzrT[n*80 + q*8];
    }
    for (int i = tid; i < 128*10; i += 256) {
        int nl = i / 10, q = i % 10;
        int n = nb + nl;
        uint4 v = make_uint4(0u,0u,0u,0u);
        if (n < Nn)
            v = (q < 2) ? *(const uint4*)&g_PxH[n*FT + t*16 + q*8]
                        : *(const uint4*)&g_PhH[n*Hh + (q-2)*8];
        *(uint4*)&Ash[nl*88 + q*8] = v;
    }
    __syncthreads();

    float acc[2][8][4];
    #pragma unroll
    for (int mi = 0; mi < 2; mi++)
        #pragma unroll
        for (int tn = 0; tn < 8; tn++)
            #pragma unroll
            for (int q = 0; q < 4; q++) acc[mi][tn][q] = 0.f;

    int m0 = wm*32;
    #pragma unroll
    for (int k16 = 0; k16 < 5; k16++) {
        int k0 = k16*16;
        uint32_t a[2][4];
        #pragma unroll
        for (int mi = 0; mi < 2; mi++) {
            uint32_t addr = smemu32(&Ash[(m0 + mi*16 + (lane & 15))*88 + k0 + (lane >> 4)*8]);
            ldmA4(a[mi], addr);
        }
        #pragma unroll
        for (int tn = 0; tn < 8; tn++) {
            const __half* bp = &Wsh[(wn*64 + tn*8 + (lane >> 2))*88 + k0 + (lane & 3)*2];
            uint32_t b0 = *(const uint32_t*)bp;
            uint32_t b1 = *(const uint32_t*)(bp + 8);
            mma16816(acc[0][tn], a[0], b0, b1);
            mma16816(acc[1][tn], a[1], b0, b1);
        }
    }

    #pragma unroll
    for (int mi = 0; mi < 2; mi++) {
        #pragma unroll
        for (int tn = 0; tn < 8; tn++) {
            int r0 = nb + m0 + mi*16 + (lane >> 2);
            int cc = wn*64 + tn*8 + (lane & 3)*2;
            float b0f = bsh[cc], b1f = bsh[cc+1];
            #pragma unroll
            for (int rr = 0; rr < 2; rr++) {
                int r = r0 + rr*8;
                if (r >= Nn) continue;
                float s0 = fsigmoid(acc[mi][tn][rr*2+0] + b0f);
                float s1 = fsigmoid(acc[mi][tn][rr*2+1] + b1f);
                if (cc < 64) {
                    *(float2*)&g_z[r*Hh + cc] = make_float2(s0, s1);
                } else {
                    int c = cc - 64;
                    float2 hv = *(const float2*)&g_h[r*Hh + c];
                    *(__half2*)&g_rhH[r*Hh + c] = __floats2half2_rn(s0*hv.x, s1*hv.y);
                }
            }
        }
    }
}

// final: [Px_t | Prh] (128 nodes x 80) @ Wh^T (64x80) -> h update, hs, hH
// 8 warps, wm 0..7 (m16 each), each covers all 64 N cols.
__global__ __launch_bounds__(256) void k_final_mma(const float* __restrict__ bh, int t)
{
    __shared__ __half Ash[128*88];   // 22528 B
    __shared__ __half Wsh[64*88];    // 11264 B
    __shared__ float  bsh[64];
    int tid = threadIdx.x;
    int lane = tid & 31, wm = tid >> 5;
    int nb = blockIdx.x * 128;

    if (tid < 64) bsh[tid] = bh[tid];
    for (int i = tid; i < 64*10; i += 256) {
        int n = i / 10, q = i % 10;
        *(uint4*)&Wsh[n*88 + q*8] = *(const uint4*)&g_WhT[n*80 + q*8];
    }
    for (int i = tid; i < 128*10; i += 256) {
        int nl = i / 10, q = i % 10;
        int n = nb + nl;
        uint4 v = make_uint4(0u,0u,0u,0u);
        if (n < Nn)
            v = (q < 2) ? *(const uint4*)&g_PxH[n*FT + t*16 + q*8]
                        : *(const uint4*)&g_PrhH[n*Hh + (q-2)*8];
        *(uint4*)&Ash[nl*88 + q*8] = v;
    }
    __syncthreads();

    float acc[8][4];
    #pragma unroll
    for (int tn = 0; tn < 8; tn++)
        #pragma unroll
        for (int q = 0; q < 4; q++) acc[tn][q] = 0.f;

    int m0 = wm*16;
    #pragma unroll
    for (int k16 = 0; k16 < 5; k16++) {
        int k0 = k16*16;
        uint32_t a[4];
        uint32_t addr = smemu32(&Ash[(m0 + (lane & 15))*88 + k0 + (lane >> 4)*8]);
        ldmA4(a, addr);
        #pragma unroll
        for (int tn = 0; tn < 8; tn++) {
            const __half* bp = &Wsh[(tn*8 + (lane >> 2))*88 + k0 + (lane & 3)*2];
            uint32_t b0 = *(const uint32_t*)bp;
            uint32_t b1 = *(const uint32_t*)(bp + 8);
            mma16816(acc[tn], a, b0, b1);
        }
    }

    #pragma unroll
    for (int tn = 0; tn < 8; tn++) {
        int r0 = nb + m0 + (lane >> 2);
        int cc = tn*8 + (lane & 3)*2;
        float b0f = bsh[cc], b1f = bsh[cc+1];
        #pragma unroll
        for (int rr = 0; rr < 2; rr++) {
            int r = r0 + rr*8;
            if (r >= Nn) continue;
            float v0 = acc[tn][rr*2+0] + b0f;
            float v1 = acc[tn][rr*2+1] + b1f;
            float2 zv = *(const float2*)&g_z[r*Hh + cc];
            float2 hv = *(const float2*)&g_h[r*Hh + cc];
            float hn0 = zv.x*hv.x + (1.f - zv.x)*ftanh(v0);
            float hn1 = zv.y*hv.y + (1.f - zv.y)*ftanh(v1);
            *(float2*)&g_h[r*Hh + cc] = make_float2(hn0, hn1);
            *(float2*)&g_hs[r*(Tt*Hh) + t*Hh + cc] = make_float2(hn0, hn1);
            *(__half2*)&g_hH[r*Hh + cc] = __floats2half2_rn(hn0, hn1);
        }
    }
}

// ---------------- temporal attention + FC ------------------------------------
__global__ __launch_bounds__(256) void k_attn(
    const float* __restrict__ Wa, const float* __restrict__ ba,
    const float* __restrict__ cv, const float* __restrict__ Wfc,
    const float* __restrict__ bfc, float* __restrict__ out)
{
    __shared__ float Wa_sh[64*64];
    __shared__ float hs_sh[4][Tt*64];
    __shared__ float part[4][64*Tt];
    __shared__ float al_sh[4][Tt];
    __shared__ float cv_sh[64], ba_sh[64], Wfc_sh[64];
    __shared__ float redbuf[4][2];

    int tid = threadIdx.x;
    int nl  = tid >> 6;
    int j   = tid & 63;
    int n   = blockIdx.x * 4 + nl;
    bool valid = n < Nn;

    for (int i = tid; i < 4096; i += 256) Wa_sh[i] = Wa[i];
    if (tid < 64) { cv_sh[tid] = cv[tid]; ba_sh[tid] = ba[tid]; Wfc_sh[tid] = Wfc[tid]; }
    #pragma unroll
    for (int t = 0; t < Tt; t++)
        hs_sh[nl][t*64 + j] = valid ? g_hs[n*(Tt*Hh) + t*Hh + j] : 0.f;
    __syncthreads();

    #pragma unroll
    for (int t = 0; t < Tt; t++) {
        float acc = ba_sh[j];
        #pragma unroll 8
        for (int k = 0; k < 64; k++)
            acc += hs_sh[nl][t*64 + k] * Wa_sh[k*64 + j];
        part[nl][j*Tt + t] = ftanh(acc) * cv_sh[j];
    }
    __syncthreads();

    if (j < Tt) {
        float s = 0.f;
        #pragma unroll
        for (int q = 0; q < 64; q++) s += part[nl][q*Tt + j];
        al_sh[nl][j] = s;
    }
    __syncthreads();

    if (j == 0) {
        float m = -1e30f;
        #pragma unroll
        for (int t = 0; t < Tt; t++) m = fmaxf(m, al_sh[nl][t]);
        float e[Tt], ssum = 0.f;
        #pragma unroll
        for (int t = 0; t < Tt; t++) { e[t] = __expf(al_sh[nl][t] - m); ssum += e[t]; }
        float inv = 1.f / ssum;
        #pragma unroll
        for (int t = 0; t < Tt; t++) al_sh[nl][t] = e[t] * inv;
    }
    __syncthreads();

    float ctx = 0.f;
    #pragma unroll
    for (int t = 0; t < Tt; t++) ctx += al_sh[nl][t] * hs_sh[nl][t*64 + j];
    float o = ctx * Wfc_sh[j];
    #pragma unroll
    for (int off = 16; off; off >>= 1) o += __shfl_down_sync(0xffffffffu, o, off);
    if ((tid & 31) == 0) redbuf[nl][(tid >> 5) & 1] = o;
    __syncthreads();
    if (j == 0 && valid) out[n] = redbuf[nl][0] + redbuf[nl][1] + bfc[0];
}

// ---------------- launch ------------------------------------------------------
extern "C" void kernel_launch(void* const* d_in, const int* in_sizes, int n_in,
                              void* d_out, int out_size) {
    const float* x   = (const float*)d_in[0];
    const int*   ei  = (const int*)  d_in[1];
    const float* ew  = (const float*)d_in[2];
    const float* Wz  = (const float*)d_in[3];
    const float* bz  = (const float*)d_in[4];
    const float* Wr  = (const float*)d_in[5];
    const float* br  = (const float*)d_in[6];
    const float* Wh  = (const float*)d_in[7];
    const float* bh  = (const float*)d_in[8];
    const float* Wa  = (const float*)d_in[9];
    const float* ba  = (const float*)d_in[10];
    const float* cv  = (const float*)d_in[11];
    const float* Wfc = (const float*)d_in[12];
    const float* bfc = (const float*)d_in[13];
    float* out = (float*)d_out;

    k_init<<<(Nn*Hh + 255)/256, 256>>>();
    k_deg <<<(Ee + 255)/256, 256>>>(ei, ew);
    k_norm<<<(Nn + 255)/256, 256>>>();
    k_ewn <<<(Ee + 255)/256, 256>>>(ei, ew);
    k_scan<<<1, SCAN_TPB>>>();
    k_scatter<<<(Ee + 255)/256, 256>>>(ei);
    k_xT  <<<(Nn*FT + 255)/256, 256>>>(x);
    k_wcvt<<<(128*80 + 255)/256, 256>>>(Wz, Wr, Wh);

    const int propBlocks = (Nn + 31)/32;    // 1563
    k_prop192_csr<<<propBlocks, 256>>>();

    const int mmaBlocks = (Nn + 127)/128;   // 391
    for (int t = 0; t < Tt; t++) {
        if (t > 0) k_prop64_csr<<<propBlocks, 256>>>(0);   // hH -> PhH
        k_gates_mma<<<mmaBlocks, 256>>>(bz, br, t);        // z, rhH
        if (t > 0) k_prop64_csr<<<propBlocks, 256>>>(1);   // rhH -> PrhH
        k_final_mma<<<mmaBlocks, 256>>>(bh, t);            // h, hH, hs
    }

    k_attn<<<(Nn + 3)/4, 256>>>(Wa, ba, cv, Wfc, bfc, out);
}